// round 14
// baseline (speedup 1.0000x reference)
#include <cuda_runtime.h>
#include <cstdint>

// Problem constants
#define B_    128
#define T_    512
#define DIN   512
#define DOUT  512
#define BETA  0.95f
#define THRESH 1.0f

#define M_TOTAL (B_ * T_)                 // 65536
#define N_SPK   ((size_t)B_ * T_ * DOUT)  // 33554432

// Scratch: currents [M, DOUT] fp32 (134 MB). __device__ global = allowed.
__device__ float g_cur[(size_t)M_TOTAL * DOUT];
__device__ int   g_count;
__device__ int   g_done;

// ---------------------------------------------------------------------------
// GEMM tiling: 128x128x16, 256 threads, 8x8 microtile per thread.
// Packed fma.rn.f32x2 (FFMA2): two IEEE fp32 RN FMAs per instruction,
// bit-identical per lane to scalar fmaf chains in the same (ascending-k)
// order. Proven rel_err 0.0 (R9/R12); measured at ~98% of FFMA2 issue ceiling.
// ---------------------------------------------------------------------------
#define BM 128
#define BN 128
#define BK 16
#define NKT (DIN / BK)        // 32 k-tiles
#define LDS_STRIDE 132        // padded row stride (floats) -> conflict-free

typedef unsigned long long ull;

static __device__ __forceinline__ ull splat2(float v) {
    ull r;
    asm("mov.b64 %0, {%1, %1};" : "=l"(r) : "f"(v));
    return r;
}
static __device__ __forceinline__ ull fma2(ull a, ull b, ull c) {
    ull d;
    asm("fma.rn.f32x2 %0, %1, %2, %3;" : "=l"(d) : "l"(a), "l"(b), "l"(c));
    return d;
}
static __device__ __forceinline__ float2 unpack2(ull v) {
    float lo, hi;
    asm("mov.b64 {%0, %1}, %2;" : "=f"(lo), "=f"(hi) : "l"(v));
    return make_float2(lo, hi);
}

__global__ __launch_bounds__(256, 2)
void gemm_kernel(const float* __restrict__ A,
                 const float* __restrict__ W,
                 const float* __restrict__ bias)
{
    // fold former zero_count_kernel here: GEMM fully precedes scan in stream
    // order, so any GEMM thread may reset the scan's counters.
    if (blockIdx.x == 0 && blockIdx.y == 0 && threadIdx.x == 0) {
        g_count = 0;
        g_done  = 0;
    }

    __shared__ float As[2][BK * LDS_STRIDE];   // As[buf][k*132 + m]
    __shared__ float Bs[2][BK * LDS_STRIDE];   // Bs[buf][k*132 + n]

    const int tid = threadIdx.x;
    const int tx  = tid & 15;       // n microtile (8 cols)
    const int ty  = tid >> 4;       // m microtile (8 rows)
    const int m0  = blockIdx.y * BM;
    const int n0  = blockIdx.x * BN;

    ull acc2[8][4];
    #pragma unroll
    for (int i = 0; i < 8; i++)
        #pragma unroll
        for (int j = 0; j < 4; j++) acc2[i][j] = 0ull;

    const int l_row = tid >> 2;             // 0..63 (+64 on second it)
    const int l_kq  = tid & 3;              // float4 within BK

    float4 pa[2], pb[2];
    #pragma unroll
    for (int it = 0; it < 2; it++) {
        int row = l_row + it * 64;
        pa[it] = *(const float4*)(&A[(size_t)(m0 + row) * DIN + l_kq * 4]);
        pb[it] = *(const float4*)(&W[(size_t)(n0 + row) * DIN + l_kq * 4]);
    }
    #pragma unroll
    for (int it = 0; it < 2; it++) {
        int row = l_row + it * 64;
        As[0][(l_kq * 4 + 0) * LDS_STRIDE + row] = pa[it].x;
        As[0][(l_kq * 4 + 1) * LDS_STRIDE + row] = pa[it].y;
        As[0][(l_kq * 4 + 2) * LDS_STRIDE + row] = pa[it].z;
        As[0][(l_kq * 4 + 3) * LDS_STRIDE + row] = pa[it].w;
        Bs[0][(l_kq * 4 + 0) * LDS_STRIDE + row] = pb[it].x;
        Bs[0][(l_kq * 4 + 1) * LDS_STRIDE + row] = pb[it].y;
        Bs[0][(l_kq * 4 + 2) * LDS_STRIDE + row] = pb[it].z;
        Bs[0][(l_kq * 4 + 3) * LDS_STRIDE + row] = pb[it].w;
    }
    __syncthreads();

    for (int kt = 0; kt < NKT; kt++) {
        const int buf = kt & 1;
        const bool pf = (kt + 1 < NKT);

        if (pf) {
            const int k0 = (kt + 1) * BK;
            #pragma unroll
            for (int it = 0; it < 2; it++) {
                int row = l_row + it * 64;
                pa[it] = *(const float4*)(&A[(size_t)(m0 + row) * DIN + k0 + l_kq * 4]);
                pb[it] = *(const float4*)(&W[(size_t)(n0 + row) * DIN + k0 + l_kq * 4]);
            }
        }

        // ---- compute on buf: ascending k, packed FFMA2 ----
        #pragma unroll
        for (int k = 0; k < BK; k++) {
            const float* ar = &As[buf][k * LDS_STRIDE + ty * 8];
            const float* br = &Bs[buf][k * LDS_STRIDE + tx * 8];
            float4 ra0 = *(const float4*)(ar);
            float4 ra1 = *(const float4*)(ar + 4);
            ulonglong2 rb0 = *(const ulonglong2*)(br);
            ulonglong2 rb1 = *(const ulonglong2*)(br + 4);
            const float ras[8] = {ra0.x, ra0.y, ra0.z, ra0.w,
                                  ra1.x, ra1.y, ra1.z, ra1.w};
            #pragma unroll
            for (int i = 0; i < 8; i++) {
                const ull pav = splat2(ras[i]);
                acc2[i][0] = fma2(pav, rb0.x, acc2[i][0]);
                acc2[i][1] = fma2(pav, rb0.y, acc2[i][1]);
                acc2[i][2] = fma2(pav, rb1.x, acc2[i][2]);
                acc2[i][3] = fma2(pav, rb1.y, acc2[i][3]);
            }
        }

        if (pf) {
            const int nbuf = buf ^ 1;
            #pragma unroll
            for (int it = 0; it < 2; it++) {
                int row = l_row + it * 64;
                As[nbuf][(l_kq * 4 + 0) * LDS_STRIDE + row] = pa[it].x;
                As[nbuf][(l_kq * 4 + 1) * LDS_STRIDE + row] = pa[it].y;
                As[nbuf][(l_kq * 4 + 2) * LDS_STRIDE + row] = pa[it].z;
                As[nbuf][(l_kq * 4 + 3) * LDS_STRIDE + row] = pa[it].w;
                Bs[nbuf][(l_kq * 4 + 0) * LDS_STRIDE + row] = pb[it].x;
                Bs[nbuf][(l_kq * 4 + 1) * LDS_STRIDE + row] = pb[it].y;
                Bs[nbuf][(l_kq * 4 + 2) * LDS_STRIDE + row] = pb[it].z;
                Bs[nbuf][(l_kq * 4 + 3) * LDS_STRIDE + row] = pb[it].w;
            }
        }
        __syncthreads();
    }

    // ---- epilogue: unpack, add bias, store ----
    const int nb = n0 + tx * 8;
    float rbias[8];
    #pragma unroll
    for (int j = 0; j < 8; j++) rbias[j] = bias[nb + j];

    #pragma unroll
    for (int i = 0; i < 8; i++) {
        const size_t m = (size_t)(m0 + ty * 8 + i);
        float2 c0 = unpack2(acc2[i][0]);
        float2 c1 = unpack2(acc2[i][1]);
        float2 c2 = unpack2(acc2[i][2]);
        float2 c3 = unpack2(acc2[i][3]);
        float4 v0 = make_float4(c0.x + rbias[0], c0.y + rbias[1],
                                c1.x + rbias[2], c1.y + rbias[3]);
        float4 v1 = make_float4(c2.x + rbias[4], c2.y + rbias[5],
                                c3.x + rbias[6], c3.y + rbias[7]);
        *(float4*)(&g_cur[m * DOUT + nb])     = v0;
        *(float4*)(&g_cur[m * DOUT + nb + 4]) = v1;
    }
}

// ---------------------------------------------------------------------------
// LIF scan: __ldg loads (reorderable past out-stores: the R12 win), batch 32
// for MLP, streaming stores (__stcs) for the write-once spike buffer, and the
// former finalize_kernel folded in via a last-block-done ticket.
// Per-element arithmetic identical to the proven rel_err-0.0 scan.
// ---------------------------------------------------------------------------
#define SB 32

__global__ __launch_bounds__(256)
void scan_kernel(float* __restrict__ out, int out_size)
{
    const int g = blockIdx.x * blockDim.x + threadIdx.x;
    const int b = g >> 9;            // / DOUT
    const int d = g & 511;           // % DOUT

    const float* __restrict__ cp = g_cur + (size_t)b * T_ * DOUT + d;
    float* __restrict__       sp = out  + (size_t)b * T_ * DOUT + d;

    float mem = 0.0f;
    int cnt = 0;

    float bufA[SB], bufB[SB];

    // prologue: batch 0
    #pragma unroll
    for (int i = 0; i < SB; i++)
        bufA[i] = __ldg(cp + (size_t)i * DOUT);

    #pragma unroll 1
    for (int it = 0; it < T_ / SB; it++) {
        float* cur = (it & 1) ? bufB : bufA;
        float* nxt = (it & 1) ? bufA : bufB;
        const int t0 = it * SB;

        // issue next batch loads BEFORE this batch's stores
        if (it + 1 < T_ / SB) {
            #pragma unroll
            for (int i = 0; i < SB; i++)
                nxt[i] = __ldg(cp + (size_t)(t0 + SB + i) * DOUT);
        }

        #pragma unroll
        for (int i = 0; i < SB; i++) {
            float c = cur[i];
            mem = BETA * mem + c;
            float s = (mem > THRESH) ? 1.0f : 0.0f;
            mem -= s;
            __stcs(sp + (size_t)(t0 + i) * DOUT, s);
            cnt += (s > 0.5f) ? 1 : 0;
        }
    }

    // ---- deterministic spike-count reduction ----
    __shared__ int sh[8];
    #pragma unroll
    for (int off = 16; off > 0; off >>= 1)
        cnt += __shfl_down_sync(0xffffffffu, cnt, off);
    if ((threadIdx.x & 31) == 0) sh[threadIdx.x >> 5] = cnt;
    __syncthreads();
    if (threadIdx.x == 0) {
        int tot = 0;
        #pragma unroll
        for (int w = 0; w < 8; w++) tot += sh[w];
        atomicAdd(&g_count, tot);
        __threadfence();
        int done = atomicAdd(&g_done, 1);
        if (done == gridDim.x - 1) {
            // all blocks' g_count adds are visible (each fenced before its
            // g_done ticket); write the trailing sum element
            int total = atomicAdd(&g_count, 0);
            if ((size_t)out_size > N_SPK)
                out[N_SPK] = (float)total;
        }
    }
}

// ---------------------------------------------------------------------------
extern "C" void kernel_launch(void* const* d_in, const int* in_sizes, int n_in,
                              void* d_out, int out_size)
{
    const float* x    = (const float*)d_in[0];   // [B, T, DIN]
    const float* W    = (const float*)d_in[1];   // [DOUT, DIN]
    const float* bias = (const float*)d_in[2];   // [DOUT]
    float* out = (float*)d_out;
    (void)in_sizes; (void)n_in;

    dim3 ggrid(DOUT / BN, M_TOTAL / BM);   // (4, 512), n fastest -> x L2 reuse
    gemm_kernel<<<ggrid, 256>>>(x, W, bias);

    scan_kernel<<<(B_ * DOUT) / 256, 256>>>(out, out_size);
}